// round 15
// baseline (speedup 1.0000x reference)
#include <cuda_runtime.h>
#include <cstdint>

#define N_ROWS   16384
#define D        1024
#define D4       (D / 4)          // 256 float4 per row
#define TEMPC    0.05f
#define EPSC     1e-8f

#define THREADS     256
#define WARPS_CTA   8
#define GRID        (N_ROWS / WARPS_CTA)   // 2048 CTAs, exactly 1 row per warp
#define F4_PER_LANE (D4 / 32)              // 8

#define FP_SCALE    1073741824.0f          // 2^30 fixed-point (loss >= 0)
#define CNT_ONE     (1ULL << 52)           // completion count in high bits
#define SUM_MASK    (CNT_ONE - 1ULL)

// Global accumulator: low 52 bits fixed-point sum, bits >=52 CTA count.
// Integer adds are exact+commutative -> deterministic for any arrival order.
__device__ unsigned long long g_acc = 0ULL;

__global__ __launch_bounds__(THREADS) void byol_v15_kernel(
    const float4* __restrict__ a4, const float4* __restrict__ b4,
    float* __restrict__ out)
{
    __shared__ unsigned long long s_acc;   // packed warp sum + warp count

    const int t   = threadIdx.x;
    const int wid = t >> 5;
    const int lid = t & 31;

    const int  row = blockIdx.x * WARPS_CTA + wid;
    const long idx = (long)row * D4 + lid;

    // 16 front-batched interleaved LDG.128 issued BEFORE the init barrier,
    // so the barrier cost hides under DRAM latency.
    float4 av[F4_PER_LANE], bv[F4_PER_LANE];
    #pragma unroll
    for (int j = 0; j < F4_PER_LANE; j++) {
        av[j] = a4[idx + 32 * j];
        bv[j] = b4[idx + 32 * j];
    }

    if (t == 0) s_acc = 0ULL;
    __syncthreads();                       // hidden under in-flight loads

    float dot = 0.f, aa = 0.f, bb = 0.f;
    #pragma unroll
    for (int j = 0; j < F4_PER_LANE; j++) {
        dot += av[j].x * bv[j].x + av[j].y * bv[j].y
             + av[j].z * bv[j].z + av[j].w * bv[j].w;
        aa  += av[j].x * av[j].x + av[j].y * av[j].y
             + av[j].z * av[j].z + av[j].w * av[j].w;
        bb  += bv[j].x * bv[j].x + bv[j].y * bv[j].y
             + bv[j].z * bv[j].z + bv[j].w * bv[j].w;
    }

    #pragma unroll
    for (int off = 16; off > 0; off >>= 1) {
        dot += __shfl_xor_sync(0xffffffffu, dot, off);
        aa  += __shfl_xor_sync(0xffffffffu, aa,  off);
        bb  += __shfl_xor_sync(0xffffffffu, bb,  off);
    }

    if (lid == 0) {
        // Per-warp row loss (>= 0), fixed-point
        const float n1 = fmaxf(sqrtf(aa), EPSC);
        const float n2 = fmaxf(sqrtf(bb), EPSC);
        const float loss = 2.0f - 2.0f * (dot / (n1 * n2));
        const unsigned long long wc =
            (unsigned long long)llrintf(loss * FP_SCALE) + CNT_ONE;

        // Packed smem atomic: last-arriving warp owns the CTA total.
        const unsigned long long wold = atomicAdd(&s_acc, wc);
        if ((wold >> 52) == (unsigned long long)(WARPS_CTA - 1)) {
            const unsigned long long cta_total = (wold + wc) & SUM_MASK;

            // Global packed atomic: last-arriving CTA writes the result.
            const unsigned long long contrib = cta_total + CNT_ONE;
            const unsigned long long old = atomicAdd(&g_acc, contrib);
            if ((old >> 52) == (unsigned long long)(GRID - 1)) {
                const unsigned long long total = (old + contrib) & SUM_MASK;
                out[0] = ((float)((double)total / (double)FP_SCALE))
                         / ((float)N_ROWS * TEMPC);
                g_acc = 0ULL;   // reset for graph replay
            }
        }
    }
}

extern "C" void kernel_launch(void* const* d_in, const int* in_sizes, int n_in,
                              void* d_out, int out_size)
{
    const float4* a4 = (const float4*)d_in[0];  // online_output [16384,1024] f32
    const float4* b4 = (const float4*)d_in[1];  // target_output [16384,1024] f32
    float* out = (float*)d_out;

    byol_v15_kernel<<<GRID, THREADS>>>(a4, b4, out);
}